// round 1
// baseline (speedup 1.0000x reference)
#include <cuda_runtime.h>

// AccumulateLoss: CONTINLEN=5 pose-consistency loss over B=in_sizes[0]/90 batch.
// inputs: d_in[0] = rotas  (10, B, 3, 3) fp32
//         d_in[1] = transs (10, B, 3)    fp32
// output: d_out[0] = sum((R1@R2 - R12)^2)*50 + sum((R1@t1 + t2 - t12)^2)

#define NPAIRS 10
#define NTRIP  10
#define BETA   50.0f

// triple -> (pair(i,k), pair(k,j), pair(i,j)) flat pair ids
__device__ __constant__ int c_p1[NTRIP]  = {0,0,0,1,1,2,4,4,5,7};
__device__ __constant__ int c_p2[NTRIP]  = {4,5,6,7,8,9,7,8,9,9};
__device__ __constant__ int c_p12[NTRIP] = {1,2,3,2,3,3,5,6,6,8};

__device__ double g_acc;

__global__ void zero_acc_kernel() { g_acc = 0.0; }

__global__ void finalize_kernel(float* __restrict__ out) {
    out[0] = (float)g_acc;
}

__global__ __launch_bounds__(256)
void accum_loss_kernel(const float* __restrict__ rotas,
                       const float* __restrict__ transs,
                       int B) {
    const int b = blockIdx.x * blockDim.x + threadIdx.x;

    float loss = 0.0f;
    if (b < B) {
        // Load all 10 pair poses for this batch element into registers.
        float R[NPAIRS][9];
        float t[NPAIRS][3];
        const size_t bB9 = (size_t)b * 9;
        const size_t bB3 = (size_t)b * 3;
        const size_t PB9 = (size_t)B * 9;
        const size_t PB3 = (size_t)B * 3;
        #pragma unroll
        for (int p = 0; p < NPAIRS; p++) {
            const float* src = rotas + (size_t)p * PB9 + bB9;
            #pragma unroll
            for (int e = 0; e < 9; e++) R[p][e] = src[e];
        }
        #pragma unroll
        for (int p = 0; p < NPAIRS; p++) {
            const float* src = transs + (size_t)p * PB3 + bB3;
            #pragma unroll
            for (int e = 0; e < 3; e++) t[p][e] = src[e];
        }

        float ra = 0.0f;  // rotation loss accumulator
        float ta = 0.0f;  // translation loss accumulator
        #pragma unroll
        for (int tr = 0; tr < NTRIP; tr++) {
            const int p1  = c_p1[tr];
            const int p2  = c_p2[tr];
            const int p12 = c_p12[tr];
            // fuse_rota = R1 @ R2 ; compare with R12
            #pragma unroll
            for (int i = 0; i < 3; i++) {
                #pragma unroll
                for (int j = 0; j < 3; j++) {
                    float s = R[p1][i*3+0] * R[p2][0*3+j]
                            + R[p1][i*3+1] * R[p2][1*3+j]
                            + R[p1][i*3+2] * R[p2][2*3+j];
                    float d = s - R[p12][i*3+j];
                    ra = fmaf(d, d, ra);
                }
            }
            // fuse_trans = R1 @ t1 + t2 ; compare with t12
            #pragma unroll
            for (int i = 0; i < 3; i++) {
                float s = R[p1][i*3+0] * t[p1][0]
                        + R[p1][i*3+1] * t[p1][1]
                        + R[p1][i*3+2] * t[p1][2]
                        + t[p2][i];
                float d = s - t[p12][i];
                ta = fmaf(d, d, ta);
            }
        }
        loss = fmaf(ra, BETA, ta);
    }

    // Warp reduction (fp32 — per-thread magnitude ~4e4, 32-way sum is safe)
    #pragma unroll
    for (int off = 16; off > 0; off >>= 1)
        loss += __shfl_down_sync(0xffffffffu, loss, off);

    __shared__ double warp_sums[8];
    const int lane = threadIdx.x & 31;
    const int wid  = threadIdx.x >> 5;
    if (lane == 0) warp_sums[wid] = (double)loss;
    __syncthreads();
    if (threadIdx.x == 0) {
        double s = 0.0;
        #pragma unroll
        for (int w = 0; w < 8; w++) s += warp_sums[w];
        atomicAdd(&g_acc, s);
    }
}

extern "C" void kernel_launch(void* const* d_in, const int* in_sizes, int n_in,
                              void* d_out, int out_size) {
    const float* rotas  = (const float*)d_in[0];
    const float* transs = (const float*)d_in[1];
    float* out = (float*)d_out;

    const int B = in_sizes[0] / (NPAIRS * 9);

    zero_acc_kernel<<<1, 1>>>();
    const int threads = 256;
    const int blocks = (B + threads - 1) / threads;
    accum_loss_kernel<<<blocks, threads>>>(rotas, transs, B);
    finalize_kernel<<<1, 1>>>(out);
}

// round 2
// speedup vs baseline: 1.8762x; 1.8762x over previous
#include <cuda_runtime.h>

// AccumulateLoss: CONTINLEN=5 pose-consistency loss.
// inputs: d_in[0] = rotas  (10, B, 3, 3) fp32
//         d_in[1] = transs (10, B, 3)    fp32
// output: d_out[0] = sum((R1@R2 - R12)^2)*50 + sum((R1@t1 + t2 - t12)^2)

#define NPAIRS 10
#define NTRIP  10
#define BETA   50.0f
#define BLOCK_B 128
#define MAX_BLOCKS 32768

// triple -> (pair(i,k), pair(k,j), pair(i,j)) flat pair ids
__device__ __constant__ int c_p1[NTRIP]  = {0,0,0,1,1,2,4,4,5,7};
__device__ __constant__ int c_p2[NTRIP]  = {4,5,6,7,8,9,7,8,9,9};
__device__ __constant__ int c_p12[NTRIP] = {1,2,3,2,3,3,5,6,6,8};

__device__ double g_partials[MAX_BLOCKS];

__global__ __launch_bounds__(BLOCK_B)
void accum_loss_kernel(const float* __restrict__ rotas,
                       const float* __restrict__ transs,
                       int B) {
    // R staged through shared: per pair, a contiguous slab of BLOCK_B*9 floats.
    __shared__ float sR[NPAIRS * BLOCK_B * 9];   // 46080 B

    const int tid = threadIdx.x;
    const int b0  = blockIdx.x * BLOCK_B;
    const int nvalid = min(BLOCK_B, B - b0);

    const size_t PB9 = (size_t)B * 9;
    const size_t PB3 = (size_t)B * 3;

    // ---- Coalesced float4 copy gmem -> shared for R ----
    if (nvalid == BLOCK_B) {
        #pragma unroll
        for (int p = 0; p < NPAIRS; p++) {
            const float4* g = (const float4*)(rotas + (size_t)p * PB9 + (size_t)b0 * 9);
            float4* s = (float4*)&sR[p * BLOCK_B * 9];
            #pragma unroll
            for (int i = tid; i < BLOCK_B * 9 / 4; i += BLOCK_B)
                s[i] = g[i];
        }
    } else {
        for (int p = 0; p < NPAIRS; p++) {
            const float* g = rotas + (size_t)p * PB9 + (size_t)b0 * 9;
            float* s = &sR[p * BLOCK_B * 9];
            for (int i = tid; i < nvalid * 9; i += BLOCK_B)
                s[i] = g[i];
        }
    }
    __syncthreads();

    float loss = 0.0f;
    if (tid < nvalid) {
        const int b = b0 + tid;
        // t: 30 floats in registers (stride-3 scalar loads — only 3 wf/LDG)
        float t[NPAIRS][3];
        #pragma unroll
        for (int p = 0; p < NPAIRS; p++) {
            const float* src = transs + (size_t)p * PB3 + (size_t)b * 3;
            t[p][0] = src[0]; t[p][1] = src[1]; t[p][2] = src[2];
        }

        const float* myR = &sR[tid * 9];
        float ra = 0.0f, ta = 0.0f;
        #pragma unroll 1
        for (int tr = 0; tr < NTRIP; tr++) {
            const int p1  = c_p1[tr];
            const int p2  = c_p2[tr];
            const int p12 = c_p12[tr];
            const float* R1  = myR + p1  * BLOCK_B * 9;
            const float* R2  = myR + p2  * BLOCK_B * 9;
            const float* R12 = myR + p12 * BLOCK_B * 9;

            float r1[9], r2[9];
            #pragma unroll
            for (int e = 0; e < 9; e++) { r1[e] = R1[e]; r2[e] = R2[e]; }

            #pragma unroll
            for (int i = 0; i < 3; i++) {
                #pragma unroll
                for (int j = 0; j < 3; j++) {
                    float s = fmaf(r1[i*3+0], r2[0*3+j],
                              fmaf(r1[i*3+1], r2[1*3+j],
                                   r1[i*3+2] * r2[2*3+j]));
                    float d = s - R12[i*3+j];
                    ra = fmaf(d, d, ra);
                }
            }
            #pragma unroll
            for (int i = 0; i < 3; i++) {
                float s = fmaf(r1[i*3+0], t[p1][0],
                          fmaf(r1[i*3+1], t[p1][1],
                          fmaf(r1[i*3+2], t[p1][2], t[p2][i])));
                float d = s - t[p12][i];
                ta = fmaf(d, d, ta);
            }
        }
        loss = fmaf(ra, BETA, ta);
    }

    // Warp reduce (fp32 — 32-way sum of ~4e4-magnitude values, safe)
    #pragma unroll
    for (int off = 16; off > 0; off >>= 1)
        loss += __shfl_down_sync(0xffffffffu, loss, off);

    __shared__ double warp_sums[BLOCK_B / 32];
    const int lane = tid & 31;
    const int wid  = tid >> 5;
    if (lane == 0) warp_sums[wid] = (double)loss;
    __syncthreads();
    if (tid == 0) {
        double s = 0.0;
        #pragma unroll
        for (int w = 0; w < BLOCK_B / 32; w++) s += warp_sums[w];
        g_partials[blockIdx.x] = s;
    }
}

__global__ __launch_bounds__(256)
void finalize_kernel(float* __restrict__ out, int nblocks) {
    double s = 0.0;
    for (int i = threadIdx.x; i < nblocks; i += 256)
        s += g_partials[i];
    #pragma unroll
    for (int off = 16; off > 0; off >>= 1)
        s += __shfl_down_sync(0xffffffffu, s, off);
    __shared__ double ws[8];
    const int lane = threadIdx.x & 31;
    const int wid  = threadIdx.x >> 5;
    if (lane == 0) ws[wid] = s;
    __syncthreads();
    if (threadIdx.x == 0) {
        double tot = 0.0;
        #pragma unroll
        for (int w = 0; w < 8; w++) tot += ws[w];
        out[0] = (float)tot;
    }
}

extern "C" void kernel_launch(void* const* d_in, const int* in_sizes, int n_in,
                              void* d_out, int out_size) {
    const float* rotas  = (const float*)d_in[0];
    const float* transs = (const float*)d_in[1];
    float* out = (float*)d_out;

    const int B = in_sizes[0] / (NPAIRS * 9);
    const int blocks = (B + BLOCK_B - 1) / BLOCK_B;   // 2048 for B=262144

    accum_loss_kernel<<<blocks, BLOCK_B>>>(rotas, transs, B);
    finalize_kernel<<<1, 256>>>(out, blocks);
}

// round 3
// speedup vs baseline: 1.9195x; 1.0231x over previous
#include <cuda_runtime.h>

// AccumulateLoss: CONTINLEN=5 pose-consistency loss.
// inputs: d_in[0] = rotas  (10, B, 3, 3) fp32
//         d_in[1] = transs (10, B, 3)    fp32
// output: d_out[0] = sum((R1@R2 - R12)^2)*50 + sum((R1@t1 + t2 - t12)^2)

#define NPAIRS 10
#define NTRIP  10
#define BETA   50.0f
#define BLOCK_B 128
#define NBLOCKS 592   // 148 SMs x 4 resident CTAs -> one persistent wave

// triple -> (pair(i,k), pair(k,j), pair(i,j)) flat pair ids
__device__ __constant__ int c_p1[NTRIP]  = {0,0,0,1,1,2,4,4,5,7};
__device__ __constant__ int c_p2[NTRIP]  = {4,5,6,7,8,9,7,8,9,9};
__device__ __constant__ int c_p12[NTRIP] = {1,2,3,2,3,3,5,6,6,8};

__device__ double g_acc;              // zero-init; reset by last block each launch
__device__ unsigned int g_counter;    // zero-init; reset by last block each launch

__global__ __launch_bounds__(BLOCK_B)
void accum_loss_kernel(const float* __restrict__ rotas,
                       const float* __restrict__ transs,
                       float* __restrict__ out,
                       int B, int ntiles, int nblocks) {
    __shared__ float sR[NPAIRS * BLOCK_B * 9];   // 46080 B -> 4 CTAs/SM

    const int tid  = threadIdx.x;
    const int lane = tid & 31;
    const int wid  = tid >> 5;

    const size_t PB9 = (size_t)B * 9;
    const size_t PB3 = (size_t)B * 3;

    float loss = 0.0f;   // per-thread across all tiles (magnitude ~1e5, fp32 ok)

    for (int tile = blockIdx.x; tile < ntiles; tile += nblocks) {
        const int b0 = tile * BLOCK_B;
        const int nvalid = min(BLOCK_B, B - b0);

        __syncthreads();   // prior tile's readers done before overwrite

        // ---- Coalesced staging of R into shared ----
        if (nvalid == BLOCK_B) {
            #pragma unroll
            for (int p = 0; p < NPAIRS; p++) {
                const float4* g = (const float4*)(rotas + (size_t)p * PB9 + (size_t)b0 * 9);
                float4* s = (float4*)&sR[p * BLOCK_B * 9];
                #pragma unroll
                for (int i = tid; i < BLOCK_B * 9 / 4; i += BLOCK_B)
                    s[i] = g[i];
            }
        } else {
            for (int p = 0; p < NPAIRS; p++) {
                const float* g = rotas + (size_t)p * PB9 + (size_t)b0 * 9;
                float* s = &sR[p * BLOCK_B * 9];
                for (int i = tid; i < nvalid * 9; i += BLOCK_B)
                    s[i] = g[i];
            }
        }
        __syncthreads();

        if (tid < nvalid) {
            const int b = b0 + tid;
            float t[NPAIRS][3];
            #pragma unroll
            for (int p = 0; p < NPAIRS; p++) {
                const float* src = transs + (size_t)p * PB3 + (size_t)b * 3;
                t[p][0] = src[0]; t[p][1] = src[1]; t[p][2] = src[2];
            }

            const float* myR = &sR[tid * 9];
            float ra = 0.0f, ta = 0.0f;
            #pragma unroll 1
            for (int tr = 0; tr < NTRIP; tr++) {
                const int p1  = c_p1[tr];
                const int p2  = c_p2[tr];
                const int p12 = c_p12[tr];
                const float* R1  = myR + p1  * BLOCK_B * 9;
                const float* R2  = myR + p2  * BLOCK_B * 9;
                const float* R12 = myR + p12 * BLOCK_B * 9;

                float r1[9], r2[9];
                #pragma unroll
                for (int e = 0; e < 9; e++) { r1[e] = R1[e]; r2[e] = R2[e]; }

                #pragma unroll
                for (int i = 0; i < 3; i++) {
                    #pragma unroll
                    for (int j = 0; j < 3; j++) {
                        float s = fmaf(r1[i*3+0], r2[0*3+j],
                                  fmaf(r1[i*3+1], r2[1*3+j],
                                       r1[i*3+2] * r2[2*3+j]));
                        float d = s - R12[i*3+j];
                        ra = fmaf(d, d, ra);
                    }
                }
                #pragma unroll
                for (int i = 0; i < 3; i++) {
                    float s = fmaf(r1[i*3+0], t[p1][0],
                              fmaf(r1[i*3+1], t[p1][1],
                              fmaf(r1[i*3+2], t[p1][2], t[p2][i])));
                    float d = s - t[p12][i];
                    ta = fmaf(d, d, ta);
                }
            }
            loss += fmaf(ra, BETA, ta);
        }
    }

    // ---- Block reduction ----
    #pragma unroll
    for (int off = 16; off > 0; off >>= 1)
        loss += __shfl_down_sync(0xffffffffu, loss, off);

    __shared__ double warp_sums[BLOCK_B / 32];
    __shared__ bool is_last;
    if (lane == 0) warp_sums[wid] = (double)loss;
    __syncthreads();

    if (tid == 0) {
        double s = 0.0;
        #pragma unroll
        for (int w = 0; w < BLOCK_B / 32; w++) s += warp_sums[w];
        atomicAdd(&g_acc, s);
        __threadfence();
        unsigned int done = atomicAdd(&g_counter, 1u);
        is_last = (done == (unsigned)nblocks - 1u);
    }
    __syncthreads();

    // ---- Last block writes the result and resets state for the next replay ----
    if (is_last && tid == 0) {
        // atomicExch reads the fully-accumulated value AND zeroes it for next launch
        unsigned long long old = atomicExch((unsigned long long*)&g_acc, 0ull);
        out[0] = (float)__longlong_as_double((long long)old);
        __threadfence();
        g_counter = 0u;
    }
}

extern "C" void kernel_launch(void* const* d_in, const int* in_sizes, int n_in,
                              void* d_out, int out_size) {
    const float* rotas  = (const float*)d_in[0];
    const float* transs = (const float*)d_in[1];
    float* out = (float*)d_out;

    const int B = in_sizes[0] / (NPAIRS * 9);
    const int ntiles = (B + BLOCK_B - 1) / BLOCK_B;
    const int nblocks = (ntiles < NBLOCKS) ? ntiles : NBLOCKS;

    accum_loss_kernel<<<nblocks, BLOCK_B>>>(rotas, transs, out, B, ntiles, nblocks);
}

// round 5
// speedup vs baseline: 2.6786x; 1.3955x over previous
#include <cuda_runtime.h>
#include <cstdint>

// AccumulateLoss: CONTINLEN=5 pose-consistency loss.
// inputs: d_in[0] = rotas  (10, B, 3, 3) fp32
//         d_in[1] = transs (10, B, 3)    fp32
// output: d_out[0] = sum((R1@R2 - R12)^2)*50 + sum((R1@t1 + t2 - t12)^2)

#define NPAIRS 10
#define NTRIP  10
#define BETA   50.0f
#define BLOCK_B 64
#define NBLOCKS 592          // 148 SMs x 4 resident CTAs
#define RSLAB   (BLOCK_B * 9)        // floats per pair slab (576)
#define RBUF    (NPAIRS * RSLAB)     // floats per buffer (5760 = 23040 B)

// triples (i,k,j) flattened to pair ids: (p1, p2, p12) — literal constants.
#define FOR_EACH_TRIPLE(X) \
    X(0,4,1) X(0,5,2) X(0,6,3) X(1,7,2) X(1,8,3) \
    X(2,9,3) X(4,7,5) X(4,8,6) X(5,9,6) X(7,9,8)

__device__ double g_acc;              // zero-init; reset by last block each launch
__device__ unsigned int g_counter;    // zero-init; reset by last block each launch

__device__ __forceinline__ uint32_t smem_u32(const void* p) {
    return (uint32_t)__cvta_generic_to_shared(p);
}
__device__ __forceinline__ void cp_async16(uint32_t s, const void* g) {
    asm volatile("cp.async.cg.shared.global [%0], [%1], 16;\n" :: "r"(s), "l"(g));
}
__device__ __forceinline__ void cp_async4(uint32_t s, const void* g) {
    asm volatile("cp.async.ca.shared.global [%0], [%1], 4;\n" :: "r"(s), "l"(g));
}
__device__ __forceinline__ void cp_commit() {
    asm volatile("cp.async.commit_group;\n" ::: "memory");
}
__device__ __forceinline__ void cp_wait1() {
    asm volatile("cp.async.wait_group 1;\n" ::: "memory");
}

__global__ __launch_bounds__(BLOCK_B)
void accum_loss_kernel(const float* __restrict__ rotas,
                       const float* __restrict__ transs,
                       float* __restrict__ out,
                       int B, int ntiles, int nblocks) {
    __shared__ float sR[2][RBUF];     // 2 x 23040 B -> 4 CTAs/SM

    const int tid  = threadIdx.x;
    const int lane = tid & 31;
    const int wid  = tid >> 5;

    const size_t PB9 = (size_t)B * 9;
    const size_t PB3 = (size_t)B * 3;

    // ---- prefetch helper: stage R for one tile into buffer `buf` ----
    auto prefetch = [&](int tile, int buf) {
        const int b0 = tile * BLOCK_B;
        const int nvalid = min(BLOCK_B, B - b0);
        if (nvalid == BLOCK_B) {
            #pragma unroll
            for (int p = 0; p < NPAIRS; p++) {
                const float4* g = (const float4*)(rotas + (size_t)p * PB9 + (size_t)b0 * 9);
                uint32_t s = smem_u32(&sR[buf][p * RSLAB]);
                #pragma unroll
                for (int i = tid; i < RSLAB / 4; i += BLOCK_B)       // 144 float4s
                    cp_async16(s + i * 16, g + i);
            }
        } else {
            for (int p = 0; p < NPAIRS; p++) {
                const float* g = rotas + (size_t)p * PB9 + (size_t)b0 * 9;
                uint32_t s = smem_u32(&sR[buf][p * RSLAB]);
                for (int i = tid; i < nvalid * 9; i += BLOCK_B)
                    cp_async4(s + i * 4, g + i);
            }
        }
    };

    float loss = 0.0f;

    int tile = blockIdx.x;
    int buf = 0;
    if (tile < ntiles) prefetch(tile, 0);
    cp_commit();

    for (; tile < ntiles; tile += nblocks) {
        const int b0 = tile * BLOCK_B;
        const int nvalid = min(BLOCK_B, B - b0);

        // t loads (registers, direct LDG) — issued before the wait so their
        // DRAM latency overlaps the wait for this tile's R slab.
        float t[NPAIRS][3];
        if (tid < nvalid) {
            const int b = b0 + tid;
            #pragma unroll
            for (int p = 0; p < NPAIRS; p++) {
                const float* src = transs + (size_t)p * PB3 + (size_t)b * 3;
                t[p][0] = src[0]; t[p][1] = src[1]; t[p][2] = src[2];
            }
        }

        // prefetch next tile into the other buffer (all reads of that buffer
        // finished at the trailing __syncthreads of the previous iteration)
        const int nxt = tile + nblocks;
        if (nxt < ntiles) prefetch(nxt, buf ^ 1);
        cp_commit();            // exactly one group per iteration (may be empty)

        cp_wait1();             // all groups but the newest done -> this tile ready
        __syncthreads();

        if (tid < nvalid) {
            // Pull all 10 R matrices into registers: 90 conflict-free LDS
            float r[NPAIRS][9];
            const float* myR = &sR[buf][tid * 9];
            #pragma unroll
            for (int p = 0; p < NPAIRS; p++) {
                #pragma unroll
                for (int e = 0; e < 9; e++)
                    r[p][e] = myR[p * RSLAB + e];
            }

            float ra = 0.0f, ta = 0.0f;

            #define DO_TRIPLE(p1, p2, p12)                                     \
            {                                                                  \
                _Pragma("unroll")                                              \
                for (int i = 0; i < 3; i++) {                                  \
                    _Pragma("unroll")                                          \
                    for (int j = 0; j < 3; j++) {                              \
                        float s = fmaf(r[p1][i*3+0], r[p2][0*3+j],             \
                                  fmaf(r[p1][i*3+1], r[p2][1*3+j],             \
                                       r[p1][i*3+2] * r[p2][2*3+j]));          \
                        float d = s - r[p12][i*3+j];                           \
                        ra = fmaf(d, d, ra);                                   \
                    }                                                          \
                }                                                              \
                _Pragma("unroll")                                              \
                for (int i = 0; i < 3; i++) {                                  \
                    float s = fmaf(r[p1][i*3+0], t[p1][0],                     \
                              fmaf(r[p1][i*3+1], t[p1][1],                     \
                              fmaf(r[p1][i*3+2], t[p1][2], t[p2][i])));        \
                    float d = s - t[p12][i];                                   \
                    ta = fmaf(d, d, ta);                                       \
                }                                                              \
            }

            FOR_EACH_TRIPLE(DO_TRIPLE)
            #undef DO_TRIPLE

            loss += fmaf(ra, BETA, ta);
        }

        __syncthreads();        // everyone done reading sR[buf] before it is refilled
        buf ^= 1;
    }

    // ---- Block reduction ----
    #pragma unroll
    for (int off = 16; off > 0; off >>= 1)
        loss += __shfl_down_sync(0xffffffffu, loss, off);

    __shared__ double warp_sums[BLOCK_B / 32];
    __shared__ bool is_last;
    if (lane == 0) warp_sums[wid] = (double)loss;
    __syncthreads();

    if (tid == 0) {
        double s = 0.0;
        #pragma unroll
        for (int w = 0; w < BLOCK_B / 32; w++) s += warp_sums[w];
        atomicAdd(&g_acc, s);
        __threadfence();
        unsigned int done = atomicAdd(&g_counter, 1u);
        is_last = (done == (unsigned)nblocks - 1u);
    }
    __syncthreads();

    // ---- Last block writes result and resets state for the next graph replay ----
    if (is_last && tid == 0) {
        unsigned long long old = atomicExch((unsigned long long*)&g_acc, 0ull);
        out[0] = (float)__longlong_as_double((long long)old);
        __threadfence();
        g_counter = 0u;
    }
}

extern "C" void kernel_launch(void* const* d_in, const int* in_sizes, int n_in,
                              void* d_out, int out_size) {
    const float* rotas  = (const float*)d_in[0];
    const float* transs = (const float*)d_in[1];
    float* out = (float*)d_out;

    const int B = in_sizes[0] / (NPAIRS * 9);
    const int ntiles = (B + BLOCK_B - 1) / BLOCK_B;   // 4096 for B=262144
    const int nblocks = (ntiles < NBLOCKS) ? ntiles : NBLOCKS;

    accum_loss_kernel<<<nblocks, BLOCK_B>>>(rotas, transs, out, B, ntiles, nblocks);
}